// round 5
// baseline (speedup 1.0000x reference)
#include <cuda_runtime.h>
#include <math.h>

// Problem constants
#define B_  16
#define N_  1024
#define IND 128
#define H_  4
#define D_  64
#define HD  256
#define NEG 0.2f

// Scratch (allocation-free rule: __device__ globals)
__device__ float g_H[B_ * N_ * HD];          // h = x@W, layout [b*N+n][head*64+d]
__device__ float g_s[B_ * N_ * H_];          // src scores
__device__ float g_t[B_ * N_ * H_];          // dst scores
__device__ float g_E[B_ * N_ * H_];          // exp(s)
__device__ float g_F[B_ * N_ * H_];          // exp(0.2 s)
__device__ float g_P[B_ * N_ * H_];          // exp(t)
__device__ float g_Q[B_ * N_ * H_];          // exp(0.2 t)

// ---------------------------------------------------------------------------
// Kernel 1: h = x @ W (per-head 64-col tile), fused s/t/exp epilogue.
// grid (M/64, H), block 256 (16x16), each thread 4x4 outputs, K-chunks of 32.
// ---------------------------------------------------------------------------
__global__ __launch_bounds__(256) void gat_gemm1(
    const float* __restrict__ x, const float* __restrict__ W,
    const float* __restrict__ a_src, const float* __restrict__ a_dst)
{
    const int head = blockIdx.y;
    const int m0   = blockIdx.x * 64;
    const int tid  = threadIdx.x;
    const int tx   = tid & 15;
    const int ty   = tid >> 4;

    __shared__ float xsT[32][68];      // transposed x tile [k][row]
    __shared__ float ws[32][68];       // W tile [k][col]
    __shared__ float asrc_s[64], adst_s[64];
    __shared__ float red[2][64][17];   // row-reduction scratch

    if (tid < 64) {
        asrc_s[tid] = a_src[head * 64 + tid];
        adst_s[tid] = a_dst[head * 64 + tid];
    }

    float acc[4][4];
#pragma unroll
    for (int i = 0; i < 4; i++)
#pragma unroll
        for (int j = 0; j < 4; j++) acc[i][j] = 0.f;

    for (int k0 = 0; k0 < IND; k0 += 32) {
        // load x tile 64 rows x 32 cols (transposed into smem)
#pragma unroll
        for (int it = 0; it < 2; ++it) {
            int idx = tid + it * 256;          // float4 index, 512 total
            int r   = idx >> 3;
            int c4  = (idx & 7) * 4;
            float4 v = *(const float4*)&x[(m0 + r) * IND + k0 + c4];
            xsT[c4 + 0][r] = v.x;
            xsT[c4 + 1][r] = v.y;
            xsT[c4 + 2][r] = v.z;
            xsT[c4 + 3][r] = v.w;
        }
        // load W tile 32 rows x 64 cols
#pragma unroll
        for (int it = 0; it < 2; ++it) {
            int idx = tid + it * 256;
            int kk  = idx >> 4;
            int c4  = (idx & 15) * 4;
            *(float4*)&ws[kk][c4] =
                *(const float4*)&W[(k0 + kk) * HD + head * 64 + c4];
        }
        __syncthreads();

#pragma unroll
        for (int kk = 0; kk < 32; ++kk) {
            float4 a4 = *(const float4*)&xsT[kk][ty * 4];
            float4 b4 = *(const float4*)&ws[kk][tx * 4];
            float a[4] = {a4.x, a4.y, a4.z, a4.w};
            float b[4] = {b4.x, b4.y, b4.z, b4.w};
#pragma unroll
            for (int i = 0; i < 4; i++)
#pragma unroll
                for (int j = 0; j < 4; j++) acc[i][j] += a[i] * b[j];
        }
        __syncthreads();
    }

    // write h + partial s/t reductions
#pragma unroll
    for (int ri = 0; ri < 4; ri++) {
        int row = ty * 4 + ri;
        float sp = 0.f, tp = 0.f;
#pragma unroll
        for (int ci = 0; ci < 4; ci++) {
            int c = tx * 4 + ci;
            sp += acc[ri][ci] * asrc_s[c];
            tp += acc[ri][ci] * adst_s[c];
        }
        red[0][row][tx] = sp;
        red[1][row][tx] = tp;
        float4 o = make_float4(acc[ri][0], acc[ri][1], acc[ri][2], acc[ri][3]);
        *(float4*)&g_H[(m0 + row) * HD + head * 64 + tx * 4] = o;
    }
    __syncthreads();

    if (tid < 64) {
        float s = 0.f, t = 0.f;
#pragma unroll
        for (int q = 0; q < 16; q++) { s += red[0][tid][q]; t += red[1][tid][q]; }
        int idx = (m0 + tid) * H_ + head;
        g_s[idx] = s;
        g_t[idx] = t;
        g_E[idx] = expf(s);
        g_F[idx] = expf(NEG * s);
        g_P[idx] = expf(t);
        g_Q[idx] = expf(NEG * t);
    }
}

// ---------------------------------------------------------------------------
// Kernel 2: fused masked softmax-weighted aggregation.
// grid (N/64, H, B), block 256. Per j-tile: build weight tile in SMEM
// (w = adj ? (s_i+t_j>=0 ? E_i*P_j : F_i*Q_j) : 0), row-sum into Z,
// register-blocked SMEM GEMM Wtile[64x64] @ Htile[64x64].
// ---------------------------------------------------------------------------
__global__ __launch_bounds__(256) void gat_attn(
    const int* __restrict__ adj, float* __restrict__ out)
{
    const int b    = blockIdx.z;
    const int head = blockIdx.y;
    const int i0   = blockIdx.x * 64;
    const int tid  = threadIdx.x;
    const int tx   = tid & 15;
    const int ty   = tid >> 4;

    __shared__ float Wt[64][68];   // weight tile transposed [j][i]
    __shared__ float sH[64][68];   // h tile [j][d]
    __shared__ float ssi[64], sE[64], sF[64];
    __shared__ float st[64], sP[64], sQ[64];
    __shared__ float sZ[64];

    if (tid < 64) {
        int idx = (b * N_ + i0 + tid) * H_ + head;
        ssi[tid] = g_s[idx];
        sE[tid]  = g_E[idx];
        sF[tid]  = g_F[idx];
        sZ[tid]  = 0.f;
    }
    __syncthreads();

    float acc[4][4];
#pragma unroll
    for (int i = 0; i < 4; i++)
#pragma unroll
        for (int j = 0; j < 4; j++) acc[i][j] = 0.f;

    const int jw = tid & 63;   // fill: this thread's j column
    const int ig = tid >> 6;   // fill: i-group 0..3

    for (int j0 = 0; j0 < N_; j0 += 64) {
        // per-j row constants
        if (tid < 64) {
            int idx = (b * N_ + j0 + tid) * H_ + head;
            st[tid] = g_t[idx];
            sP[tid] = g_P[idx];
            sQ[tid] = g_Q[idx];
        }
        // load H tile: 64 x 64 floats = 1024 float4
#pragma unroll
        for (int it = 0; it < 4; ++it) {
            int idx = tid + it * 256;
            int r   = idx >> 4;
            int c4  = (idx & 15) * 4;
            *(float4*)&sH[r][c4] =
                *(const float4*)&g_H[(b * N_ + j0 + r) * HD + head * 64 + c4];
        }
        __syncthreads();

        // build weight tile (coalesced adj reads along j)
        {
            float tj = st[jw], Pj = sP[jw], Qj = sQ[jw];
#pragma unroll
            for (int k = 0; k < 16; k++) {
                int i = ig * 16 + k;
                int a = adj[(i0 + i) * N_ + j0 + jw];
                float w = 0.f;
                if (a > 0)
                    w = (ssi[i] + tj >= 0.f) ? sE[i] * Pj : sF[i] * Qj;
                Wt[jw][i] = w;
            }
        }
        __syncthreads();

        // Z accumulation (conflict-free column reads)
        {
            int i = tid & 63, q = tid >> 6;
            float z = 0.f;
#pragma unroll
            for (int jj = q * 16; jj < q * 16 + 16; jj++) z += Wt[jj][i];
            atomicAdd(&sZ[i], z);
        }

        // GEMM: acc[i][d] += Wt[j][i] * sH[j][d]
#pragma unroll 8
        for (int jj = 0; jj < 64; jj++) {
            float4 w4 = *(const float4*)&Wt[jj][ty * 4];
            float4 h4 = *(const float4*)&sH[jj][tx * 4];
            float w[4] = {w4.x, w4.y, w4.z, w4.w};
            float h[4] = {h4.x, h4.y, h4.z, h4.w};
#pragma unroll
            for (int i = 0; i < 4; i++)
#pragma unroll
                for (int d = 0; d < 4; d++) acc[i][d] += w[i] * h[d];
        }
        __syncthreads();
    }

    // normalize and write out
#pragma unroll
    for (int ri = 0; ri < 4; ri++) {
        int i = ty * 4 + ri;
        float invZ = 1.f / sZ[i];
        float4 o = make_float4(acc[ri][0] * invZ, acc[ri][1] * invZ,
                               acc[ri][2] * invZ, acc[ri][3] * invZ);
        *(float4*)&out[(b * N_ + i0 + i) * HD + head * 64 + tx * 4] = o;
    }
}

extern "C" void kernel_launch(void* const* d_in, const int* in_sizes, int n_in,
                              void* d_out, int out_size)
{
    const float* x     = (const float*)d_in[0];
    const int*   adj   = (const int*)d_in[1];
    const float* W     = (const float*)d_in[2];
    const float* a_src = (const float*)d_in[3];
    const float* a_dst = (const float*)d_in[4];
    float*       out   = (float*)d_out;

    dim3 g1(B_ * N_ / 64, H_);
    gat_gemm1<<<g1, 256>>>(x, W, a_src, a_dst);

    dim3 g2(N_ / 64, H_, B_);
    gat_attn<<<g2, 256>>>(adj, out);
}

// round 10
// speedup vs baseline: 1.0683x; 1.0683x over previous
#include <cuda_runtime.h>
#include <math.h>

// Problem constants
#define B_  16
#define N_  1024
#define IND 128
#define H_  4
#define D_  64
#define HD  256
#define NEG 0.2f

// Scratch (allocation-free rule: __device__ globals)
__device__ float g_H[B_ * N_ * HD];          // h = x@W, layout [b*N+n][head*64+d]
__device__ float g_s[B_ * N_ * H_];          // src scores
__device__ float g_t[B_ * N_ * H_];          // dst scores
__device__ float g_E[B_ * N_ * H_];          // exp(s)
__device__ float g_F[B_ * N_ * H_];          // exp(0.2 s)
__device__ float g_P[B_ * N_ * H_];          // exp(t)
__device__ float g_Q[B_ * N_ * H_];          // exp(0.2 t)
__device__ unsigned g_mask[32 * N_];         // adjacency bitmask, [jword][i] (transposed)

// ---------------------------------------------------------------------------
// Kernel 0: adjacency -> bitmask. g_mask[w*1024 + i] bit L = (adj[i][w*32+L] > 0)
// grid = N_ blocks (one row i each), 256 threads.
// ---------------------------------------------------------------------------
__global__ __launch_bounds__(256) void gat_mask(const int* __restrict__ adj)
{
    const int i    = blockIdx.x;
    const int lane = threadIdx.x & 31;
    const int wq   = threadIdx.x >> 5;          // 0..7
#pragma unroll
    for (int it = 0; it < 4; ++it) {
        int w = it * 8 + wq;                    // 0..31
        int a = adj[i * N_ + w * 32 + lane];
        unsigned m = __ballot_sync(0xffffffffu, a > 0);
        if (lane == 0) g_mask[w * N_ + i] = m;
    }
}

// ---------------------------------------------------------------------------
// Kernel 1: h = x @ W (per-head 64-col tile), fused s/t/exp epilogue.
// grid (M/64, H), block 256 (16x16), each thread 4x4 outputs, K-chunks of 32.
// ---------------------------------------------------------------------------
__global__ __launch_bounds__(256) void gat_gemm1(
    const float* __restrict__ x, const float* __restrict__ W,
    const float* __restrict__ a_src, const float* __restrict__ a_dst)
{
    const int head = blockIdx.y;
    const int m0   = blockIdx.x * 64;
    const int tid  = threadIdx.x;
    const int tx   = tid & 15;
    const int ty   = tid >> 4;

    __shared__ float xsT[32][68];      // transposed x tile [k][row]
    __shared__ float ws[32][68];       // W tile [k][col]
    __shared__ float asrc_s[64], adst_s[64];
    __shared__ float red[2][64][17];   // row-reduction scratch

    if (tid < 64) {
        asrc_s[tid] = a_src[head * 64 + tid];
        adst_s[tid] = a_dst[head * 64 + tid];
    }

    float acc[4][4];
#pragma unroll
    for (int i = 0; i < 4; i++)
#pragma unroll
        for (int j = 0; j < 4; j++) acc[i][j] = 0.f;

    for (int k0 = 0; k0 < IND; k0 += 32) {
#pragma unroll
        for (int it = 0; it < 2; ++it) {
            int idx = tid + it * 256;
            int r   = idx >> 3;
            int c4  = (idx & 7) * 4;
            float4 v = *(const float4*)&x[(m0 + r) * IND + k0 + c4];
            xsT[c4 + 0][r] = v.x;
            xsT[c4 + 1][r] = v.y;
            xsT[c4 + 2][r] = v.z;
            xsT[c4 + 3][r] = v.w;
        }
#pragma unroll
        for (int it = 0; it < 2; ++it) {
            int idx = tid + it * 256;
            int kk  = idx >> 4;
            int c4  = (idx & 15) * 4;
            *(float4*)&ws[kk][c4] =
                *(const float4*)&W[(k0 + kk) * HD + head * 64 + c4];
        }
        __syncthreads();

#pragma unroll
        for (int kk = 0; kk < 32; ++kk) {
            float4 a4 = *(const float4*)&xsT[kk][ty * 4];
            float4 b4 = *(const float4*)&ws[kk][tx * 4];
            float a[4] = {a4.x, a4.y, a4.z, a4.w};
            float b[4] = {b4.x, b4.y, b4.z, b4.w};
#pragma unroll
            for (int i = 0; i < 4; i++)
#pragma unroll
                for (int j = 0; j < 4; j++) acc[i][j] += a[i] * b[j];
        }
        __syncthreads();
    }

#pragma unroll
    for (int ri = 0; ri < 4; ri++) {
        int row = ty * 4 + ri;
        float sp = 0.f, tp = 0.f;
#pragma unroll
        for (int ci = 0; ci < 4; ci++) {
            int c = tx * 4 + ci;
            sp += acc[ri][ci] * asrc_s[c];
            tp += acc[ri][ci] * adst_s[c];
        }
        red[0][row][tx] = sp;
        red[1][row][tx] = tp;
        float4 o = make_float4(acc[ri][0], acc[ri][1], acc[ri][2], acc[ri][3]);
        *(float4*)&g_H[(m0 + row) * HD + head * 64 + tx * 4] = o;
    }
    __syncthreads();

    if (tid < 64) {
        float s = 0.f, t = 0.f;
#pragma unroll
        for (int q = 0; q < 16; q++) { s += red[0][tid][q]; t += red[1][tid][q]; }
        int idx = (m0 + tid) * H_ + head;
        g_s[idx] = s;
        g_t[idx] = t;
        g_E[idx] = expf(s);
        g_F[idx] = expf(NEG * s);
        g_P[idx] = expf(t);
        g_Q[idx] = expf(NEG * t);
    }
}

// ---------------------------------------------------------------------------
// Kernel 2: fused masked softmax aggregation, 8x8 register blocking.
// grid (N/128, H, B), 128 threads. i-tile=128, j-tile=64.
// Build phase: thread == i (conflict-free Wt stores, register Z accumulation,
//              bitmask adjacency). GEMM phase: 16(ty,i) x 8(tx,d) thread grid,
//              8x8 per thread: 64B LDS per 64 FMA.
// Dynamic smem: Wt[64][128] + sH[64][64] + stj/sPj/sQj[64] + sZ[128]
// ---------------------------------------------------------------------------
#define ATTN_SMEM_FLOATS (64 * 128 + 64 * 64 + 3 * 64 + 128)
#define ATTN_SMEM_BYTES  (ATTN_SMEM_FLOATS * 4)

__global__ __launch_bounds__(128) void gat_attn(float* __restrict__ out)
{
    extern __shared__ float smem[];
    float* Wt  = smem;                 // [64][128]  (j, i)
    float* sHt = Wt + 64 * 128;        // [64][64]   (j, d)
    float* stj = sHt + 64 * 64;        // [64]
    float* sPj = stj + 64;             // [64]
    float* sQj = sPj + 64;             // [64]
    float* sZ  = sQj + 64;             // [128]

    const int b    = blockIdx.z;
    const int head = blockIdx.y;
    const int i0   = blockIdx.x * 128;
    const int tid  = threadIdx.x;
    const int tx   = tid & 7;          // d-group (8 groups of 8)
    const int ty   = tid >> 3;         // i-group (16 groups of 8)

    // build-phase identity: this thread owns row i = i0 + tid
    const int iidx = (b * N_ + i0 + tid) * H_ + head;
    const float si = g_s[iidx];
    const float Ei = g_E[iidx];
    const float Fi = g_F[iidx];
    float zacc = 0.f;

    float acc[8][8];
#pragma unroll
    for (int i = 0; i < 8; i++)
#pragma unroll
        for (int j = 0; j < 8; j++) acc[i][j] = 0.f;

    for (int j0 = 0; j0 < N_; j0 += 64) {
        // --- A: stage j-row constants + H tile + masks ---
        if (tid < 64) {
            int jdx = (b * N_ + j0 + tid) * H_ + head;
            stj[tid] = g_t[jdx];
            sPj[tid] = g_P[jdx];
            sQj[tid] = g_Q[jdx];
        }
#pragma unroll
        for (int it = 0; it < 8; ++it) {
            int idx = tid + it * 128;
            int r   = idx >> 4;
            int c4  = (idx & 15) * 4;
            *(float4*)&sHt[r * 64 + c4] =
                *(const float4*)&g_H[(b * N_ + j0 + r) * HD + head * 64 + c4];
        }
        unsigned m0 = g_mask[(j0 >> 5) * N_ + i0 + tid];
        unsigned m1 = g_mask[((j0 >> 5) + 1) * N_ + i0 + tid];
        unsigned long long m = (unsigned long long)m0 |
                               ((unsigned long long)m1 << 32);
        __syncthreads();   // stj visible; (prev GEMM done via loop-end sync)

        // --- C: build weight tile, row i = tid, accumulate Z in register ---
#pragma unroll 8
        for (int jw = 0; jw < 64; ++jw) {
            float w = 0.f;
            if ((m >> jw) & 1ULL) {
                float tj  = stj[jw];
                bool pos  = (si + tj) >= 0.f;
                float u   = pos ? Ei : Fi;
                float v   = pos ? sPj[jw] : sQj[jw];
                w = u * v;
            }
            Wt[jw * 128 + tid] = w;
            zacc += w;
        }
        __syncthreads();   // Wt + sHt visible to GEMM

        // --- E: GEMM acc[i][d] += Wt[j][i] * sH[j][d] ---
#pragma unroll 4
        for (int jj = 0; jj < 64; ++jj) {
            const float* wr = &Wt[jj * 128 + ty * 8];
            const float* hr = &sHt[jj * 64 + tx * 8];
            float4 w0 = *(const float4*)&wr[0];
            float4 w1 = *(const float4*)&wr[4];
            float4 h0 = *(const float4*)&hr[0];
            float4 h1 = *(const float4*)&hr[4];
            float wv[8] = {w0.x, w0.y, w0.z, w0.w, w1.x, w1.y, w1.z, w1.w};
            float hv[8] = {h0.x, h0.y, h0.z, h0.w, h1.x, h1.y, h1.z, h1.w};
#pragma unroll
            for (int i = 0; i < 8; i++)
#pragma unroll
                for (int d = 0; d < 8; d++) acc[i][d] += wv[i] * hv[d];
        }
        __syncthreads();   // GEMM done: next iter may overwrite Wt/sHt/stj
    }

    // --- epilogue: normalize by Z and store ---
    sZ[tid] = zacc;
    __syncthreads();

#pragma unroll
    for (int ri = 0; ri < 8; ri++) {
        int i = ty * 8 + ri;
        float invZ = 1.f / sZ[i];
        float* op = &out[(b * N_ + i0 + i) * HD + head * 64 + tx * 8];
        float4 o0 = make_float4(acc[ri][0] * invZ, acc[ri][1] * invZ,
                                acc[ri][2] * invZ, acc[ri][3] * invZ);
        float4 o1 = make_float4(acc[ri][4] * invZ, acc[ri][5] * invZ,
                                acc[ri][6] * invZ, acc[ri][7] * invZ);
        *(float4*)&op[0] = o0;
        *(float4*)&op[4] = o1;
    }
}

extern "C" void kernel_launch(void* const* d_in, const int* in_sizes, int n_in,
                              void* d_out, int out_size)
{
    const float* x     = (const float*)d_in[0];
    const int*   adj   = (const int*)d_in[1];
    const float* W     = (const float*)d_in[2];
    const float* a_src = (const float*)d_in[3];
    const float* a_dst = (const float*)d_in[4];
    float*       out   = (float*)d_out;

    cudaFuncSetAttribute(gat_attn, cudaFuncAttributeMaxDynamicSharedMemorySize,
                         ATTN_SMEM_BYTES);

    gat_mask<<<N_, 256>>>(adj);

    dim3 g1(B_ * N_ / 64, H_);
    gat_gemm1<<<g1, 256>>>(x, W, a_src, a_dst);

    dim3 g2(N_ / 128, H_, B_);
    gat_attn<<<g2, 128, ATTN_SMEM_BYTES>>>(out);
}

// round 12
// speedup vs baseline: 1.1177x; 1.0462x over previous
#include <cuda_runtime.h>
#include <math.h>

// Problem constants
#define B_  16
#define N_  1024
#define IND 128
#define H_  4
#define D_  64
#define HD  256
#define NEG 0.2f

typedef unsigned long long ull;

// Packed fp32x2 helpers (sm_100+ PTX; exact fp32 semantics, 2 FMAs/lane/instr)
#define FMA2(d, a, b, c) \
    asm("fma.rn.f32x2 %0, %1, %2, %3;" : "=l"(d) : "l"(a), "l"(b), "l"(c))
#define PACK2(dst, s) \
    asm("mov.b64 %0, {%1, %1};" : "=l"(dst) : "r"(__float_as_uint(s)))
#define UNPACK2(lo_, hi_, v) \
    asm("mov.b64 {%0, %1}, %2;" : "=r"(lo_), "=r"(hi_) : "l"(v))

// Scratch (allocation-free rule: __device__ globals)
__device__ float g_H[B_ * N_ * HD];          // h = x@W, layout [b*N+n][head*64+d]
__device__ float g_s[B_ * N_ * H_];          // src scores
__device__ float g_t[B_ * N_ * H_];          // dst scores
__device__ float g_E[B_ * N_ * H_];          // exp(s)
__device__ float g_F[B_ * N_ * H_];          // exp(0.2 s)
__device__ float g_P[B_ * N_ * H_];          // exp(t)
__device__ float g_Q[B_ * N_ * H_];          // exp(0.2 t)
__device__ unsigned g_mask[32 * N_];         // adjacency bitmask, [jword][i] (transposed)

// ---------------------------------------------------------------------------
// Kernel 0: adjacency -> bitmask (int4 loads, nibble pack, smem atomicOr).
// grid = N_ (one row i per block), 256 threads: thread t covers j = 4t..4t+3.
// ---------------------------------------------------------------------------
__global__ __launch_bounds__(256) void gat_mask(const int* __restrict__ adj)
{
    __shared__ unsigned words[32];
    const int i   = blockIdx.x;
    const int tid = threadIdx.x;

    if (tid < 32) words[tid] = 0u;
    __syncthreads();

    int4 v = *(const int4*)&adj[i * N_ + tid * 4];
    unsigned nib = (v.x > 0 ? 1u : 0u) | (v.y > 0 ? 2u : 0u) |
                   (v.z > 0 ? 4u : 0u) | (v.w > 0 ? 8u : 0u);
    atomicOr(&words[tid >> 3], nib << ((tid & 7) * 4));
    __syncthreads();

    if (tid < 32) g_mask[tid * N_ + i] = words[tid];
}

// ---------------------------------------------------------------------------
// Kernel 1: h = x @ W (per-head 64-col tile), fused s/t/exp epilogue.
// grid (M/64, H), block 256 (16x16), each thread 4x4 outputs, K-chunks of 32.
// ---------------------------------------------------------------------------
__global__ __launch_bounds__(256) void gat_gemm1(
    const float* __restrict__ x, const float* __restrict__ W,
    const float* __restrict__ a_src, const float* __restrict__ a_dst)
{
    const int head = blockIdx.y;
    const int m0   = blockIdx.x * 64;
    const int tid  = threadIdx.x;
    const int tx   = tid & 15;
    const int ty   = tid >> 4;

    __shared__ float xsT[32][68];      // transposed x tile [k][row]
    __shared__ float ws[32][68];       // W tile [k][col]
    __shared__ float asrc_s[64], adst_s[64];
    __shared__ float red[2][64][17];   // row-reduction scratch

    if (tid < 64) {
        asrc_s[tid] = a_src[head * 64 + tid];
        adst_s[tid] = a_dst[head * 64 + tid];
    }

    float acc[4][4];
#pragma unroll
    for (int i = 0; i < 4; i++)
#pragma unroll
        for (int j = 0; j < 4; j++) acc[i][j] = 0.f;

    for (int k0 = 0; k0 < IND; k0 += 32) {
#pragma unroll
        for (int it = 0; it < 2; ++it) {
            int idx = tid + it * 256;
            int r   = idx >> 3;
            int c4  = (idx & 7) * 4;
            float4 v = *(const float4*)&x[(m0 + r) * IND + k0 + c4];
            xsT[c4 + 0][r] = v.x;
            xsT[c4 + 1][r] = v.y;
            xsT[c4 + 2][r] = v.z;
            xsT[c4 + 3][r] = v.w;
        }
#pragma unroll
        for (int it = 0; it < 2; ++it) {
            int idx = tid + it * 256;
            int kk  = idx >> 4;
            int c4  = (idx & 15) * 4;
            *(float4*)&ws[kk][c4] =
                *(const float4*)&W[(k0 + kk) * HD + head * 64 + c4];
        }
        __syncthreads();

#pragma unroll
        for (int kk = 0; kk < 32; ++kk) {
            float4 a4 = *(const float4*)&xsT[kk][ty * 4];
            float4 b4 = *(const float4*)&ws[kk][tx * 4];
            float a[4] = {a4.x, a4.y, a4.z, a4.w};
            float b[4] = {b4.x, b4.y, b4.z, b4.w};
#pragma unroll
            for (int i = 0; i < 4; i++)
#pragma unroll
                for (int j = 0; j < 4; j++) acc[i][j] += a[i] * b[j];
        }
        __syncthreads();
    }

#pragma unroll
    for (int ri = 0; ri < 4; ri++) {
        int row = ty * 4 + ri;
        float sp = 0.f, tp = 0.f;
#pragma unroll
        for (int ci = 0; ci < 4; ci++) {
            int c = tx * 4 + ci;
            sp += acc[ri][ci] * asrc_s[c];
            tp += acc[ri][ci] * adst_s[c];
        }
        red[0][row][tx] = sp;
        red[1][row][tx] = tp;
        float4 o = make_float4(acc[ri][0], acc[ri][1], acc[ri][2], acc[ri][3]);
        *(float4*)&g_H[(m0 + row) * HD + head * 64 + tx * 4] = o;
    }
    __syncthreads();

    if (tid < 64) {
        float s = 0.f, t = 0.f;
#pragma unroll
        for (int q = 0; q < 16; q++) { s += red[0][tid][q]; t += red[1][tid][q]; }
        int idx = (m0 + tid) * H_ + head;
        g_s[idx] = s;
        g_t[idx] = t;
        g_E[idx] = expf(s);
        g_F[idx] = expf(NEG * s);
        g_P[idx] = expf(t);
        g_Q[idx] = expf(NEG * t);
    }
}

// ---------------------------------------------------------------------------
// Kernel 2: fused masked softmax aggregation, 8x8 register blocking,
// inner product via packed fma.rn.f32x2 (2 exact fp32 FMAs per instruction:
// doubles the FMA-pipe ceiling vs scalar FFMA).
// grid (N/128, H, B), 128 threads. i-tile=128, j-tile=64.
// Pairs run along d: sHt float4 loads reinterpret as 2 packed f32x2 operands;
// the w scalar is broadcast-packed with one mov.b64 per i per jj.
// ---------------------------------------------------------------------------
#define ATTN_SMEM_FLOATS (64 * 128 + 64 * 64 + 3 * 64 + 128)
#define ATTN_SMEM_BYTES  (ATTN_SMEM_FLOATS * 4)

__global__ __launch_bounds__(128) void gat_attn(float* __restrict__ out)
{
    extern __shared__ float smem[];
    float* Wt  = smem;                 // [64][128]  (j, i)
    float* sHt = Wt + 64 * 128;        // [64][64]   (j, d)
    float* stj = sHt + 64 * 64;        // [64]
    float* sPj = stj + 64;             // [64]
    float* sQj = sPj + 64;             // [64]
    float* sZ  = sQj + 64;             // [128]

    const int b    = blockIdx.z;
    const int head = blockIdx.y;
    const int i0   = blockIdx.x * 128;
    const int tid  = threadIdx.x;
    const int tx   = tid & 7;          // d-group (8 groups of 8 floats = 4 pairs x2)
    const int ty   = tid >> 3;         // i-group (16 groups of 8)

    // build-phase identity: this thread owns row i = i0 + tid
    const int iidx = (b * N_ + i0 + tid) * H_ + head;
    const float si = g_s[iidx];
    const float Ei = g_E[iidx];
    const float Fi = g_F[iidx];
    float zacc = 0.f;

    ull acc2[8][4];                    // 8 i  x  4 d-pairs (d = tx*8 .. tx*8+7)
#pragma unroll
    for (int i = 0; i < 8; i++)
#pragma unroll
        for (int d = 0; d < 4; d++) acc2[i][d] = 0ULL;

    for (int j0 = 0; j0 < N_; j0 += 64) {
        // --- A: stage j-row constants + H tile + masks ---
        if (tid < 64) {
            int jdx = (b * N_ + j0 + tid) * H_ + head;
            stj[tid] = g_t[jdx];
            sPj[tid] = g_P[jdx];
            sQj[tid] = g_Q[jdx];
        }
#pragma unroll
        for (int it = 0; it < 8; ++it) {
            int idx = tid + it * 128;
            int r   = idx >> 4;
            int c4  = (idx & 15) * 4;
            *(float4*)&sHt[r * 64 + c4] =
                *(const float4*)&g_H[(b * N_ + j0 + r) * HD + head * 64 + c4];
        }
        unsigned mw0 = g_mask[(j0 >> 5) * N_ + i0 + tid];
        unsigned mw1 = g_mask[((j0 >> 5) + 1) * N_ + i0 + tid];
        unsigned long long m = (unsigned long long)mw0 |
                               ((unsigned long long)mw1 << 32);
        __syncthreads();

        // --- C: build weight tile, row i = tid, accumulate Z in register ---
#pragma unroll 8
        for (int jw = 0; jw < 64; ++jw) {
            float w = 0.f;
            if ((m >> jw) & 1ULL) {
                float tj  = stj[jw];
                bool pos  = (si + tj) >= 0.f;
                float u   = pos ? Ei : Fi;
                float v   = pos ? sPj[jw] : sQj[jw];
                w = u * v;
            }
            Wt[jw * 128 + tid] = w;
            zacc += w;
        }
        __syncthreads();

        // --- E: GEMM acc[i][d-pair] += w2(i) * h2(d-pair), packed f32x2 ---
#pragma unroll 4
        for (int jj = 0; jj < 64; ++jj) {
            const float* wr = &Wt[jj * 128 + ty * 8];
            const ulonglong2* hp = (const ulonglong2*)&sHt[jj * 64 + tx * 8];
            ulonglong2 ha = hp[0];
            ulonglong2 hb = hp[1];
            ull hv[4] = {ha.x, ha.y, hb.x, hb.y};
            float4 w0 = *(const float4*)&wr[0];
            float4 w1 = *(const float4*)&wr[4];
            float wf[8] = {w0.x, w0.y, w0.z, w0.w, w1.x, w1.y, w1.z, w1.w};
#pragma unroll
            for (int i = 0; i < 8; i++) {
                ull wp;
                PACK2(wp, wf[i]);
#pragma unroll
                for (int d = 0; d < 4; d++)
                    FMA2(acc2[i][d], wp, hv[d], acc2[i][d]);
            }
        }
        __syncthreads();
    }

    // --- epilogue: normalize by Z and store ---
    sZ[tid] = zacc;
    __syncthreads();

#pragma unroll
    for (int ri = 0; ri < 8; ri++) {
        int i = ty * 8 + ri;
        float invZ = 1.f / sZ[i];
        float o[8];
#pragma unroll
        for (int d = 0; d < 4; d++) {
            unsigned lo, hi;
            UNPACK2(lo, hi, acc2[ri][d]);
            o[d * 2 + 0] = __uint_as_float(lo) * invZ;
            o[d * 2 + 1] = __uint_as_float(hi) * invZ;
        }
        float* op = &out[(b * N_ + i0 + i) * HD + head * 64 + tx * 8];
        *(float4*)&op[0] = make_float4(o[0], o[1], o[2], o[3]);
        *(float4*)&op[4] = make_float4(o[4], o[5], o[6], o[7]);
    }
}

extern "C" void kernel_launch(void* const* d_in, const int* in_sizes, int n_in,
                              void* d_out, int out_size)
{
    const float* x     = (const float*)d_in[0];
    const int*   adj   = (const int*)d_in[1];
    const float* W     = (const float*)d_in[2];
    const float* a_src = (const float*)d_in[3];
    const float* a_dst = (const float*)d_in[4];
    float*       out   = (float*)d_out;

    cudaFuncSetAttribute(gat_attn, cudaFuncAttributeMaxDynamicSharedMemorySize,
                         ATTN_SMEM_BYTES);

    gat_mask<<<N_, 256>>>(adj);

    dim3 g1(B_ * N_ / 64, H_);
    gat_gemm1<<<g1, 256>>>(x, W, a_src, a_dst);

    dim3 g2(N_ / 128, H_, B_);
    gat_attn<<<g2, 128, ATTN_SMEM_BYTES>>>(out);
}